// round 1
// baseline (speedup 1.0000x reference)
#include <cuda_runtime.h>
#include <cuda_bf16.h>
#include <cstdint>

// Problem constants
#define F_ 32
#define B_ 4096
#define D_ 64
#define K_ 512

// Tiling
#define BM 128      // rows per block
#define BN 128      // codes per k-chunk
#define NTHREADS 256

// Scratch (no allocations allowed -> __device__ globals)
__device__ float g_wt[(size_t)F_ * K_ * D_];   // transposed codebook [f][k][d], 4 MB
__device__ float g_wn[F_ * K_];                // 0.5 * ||w_k||^2
__device__ float g_partial[2048];              // per-block loss partial sums

// smem layout (dynamic):
//   xs  : [64][128] floats  (offset 0,      32 KB)  x tile, transposed (d-major)
//   ws  : [64][128] floats  (offset 32 KB,  32 KB)  w chunk (d-major, k contiguous)
//   wns : [128]     floats  (offset 64 KB,  512 B)  0.5||w||^2 for chunk
//   sidx: [128]     ints    (offset 64.5KB, 512 B)  final per-row argmax index
// reduction area overlays ws after the GEMM loop:
//   red_v: [128][16] floats (offset 32 KB, 8 KB)
//   red_i: [128][16] ints   (offset 40 KB, 8 KB)
#define SMEM_BYTES (64 * 128 * 4 * 2 + 512 + 512)

// ---------------------------------------------------------------------------
// Prep: wn = 0.5*sum_d w[f,d,k]^2 ; wt[f,k,d] = w[f,d,k]
// ---------------------------------------------------------------------------
__global__ void vq_prep(const float* __restrict__ w) {
    int i = blockIdx.x * blockDim.x + threadIdx.x;   // i = f*K + k
    if (i >= F_ * K_) return;
    int f = i >> 9;
    int k = i & (K_ - 1);
    const float* wf = w + (size_t)f * D_ * K_;
    float s = 0.f;
    float* wt = g_wt + (size_t)i * D_;
#pragma unroll
    for (int d = 0; d < D_; ++d) {
        float v = wf[(size_t)d * K_ + k];            // coalesced across k
        s += v * v;
        wt[d] = v;
    }
    g_wn[i] = 0.5f * s;
}

// ---------------------------------------------------------------------------
// Main: per-(f, 128-row tile) fused distance GEMM + argmax + gather + loss
// ---------------------------------------------------------------------------
__global__ __launch_bounds__(NTHREADS, 2)
void vq_main(const float* __restrict__ x,
             const float* __restrict__ w,
             float* __restrict__ out) {
    extern __shared__ float smem[];
    float* xs  = smem;                 // [64][128]
    float* ws  = smem + 64 * 128;      // [64][128]
    float* wns = smem + 2 * 64 * 128;  // [128]
    int*   sidx = (int*)(wns + 128);   // [128]
    float* red_v = ws;                 // overlays ws after GEMM
    int*   red_i = (int*)(ws + 128 * 16);

    const int f   = blockIdx.y;
    const int b0  = blockIdx.x * BM;
    const int tid = threadIdx.x;
    const int ty  = tid >> 4;          // 0..15 -> row group
    const int tx  = tid & 15;          // 0..15 -> col group

    // ---- load x tile (128 rows x 64) into xs transposed: xs[d][row] ----
    const float* xg = x + ((size_t)f * B_ + b0) * D_;
    for (int i = tid; i < BM * (D_ / 4); i += NTHREADS) {  // 2048 float4 loads
        int row = i >> 4;
        int c4  = i & 15;
        float4 v = ((const float4*)(xg + (size_t)row * D_))[c4];
        int d = c4 * 4;
        xs[(d + 0) * BM + row] = v.x;
        xs[(d + 1) * BM + row] = v.y;
        xs[(d + 2) * BM + row] = v.z;
        xs[(d + 3) * BM + row] = v.w;
    }

    float best[8];
    int   bidx[8];
#pragma unroll
    for (int i = 0; i < 8; ++i) { best[i] = -1e30f; bidx[i] = 0; }

    const float* wgf = w + (size_t)f * D_ * K_;

    for (int k0 = 0; k0 < K_; k0 += BN) {
        __syncthreads();  // protect ws/wns from prior-iteration readers

        // load w chunk: ws[d][kk] = w[f][d][k0+kk]  (already k-contiguous)
        for (int i = tid; i < D_ * (BN / 4); i += NTHREADS) {  // 2048 float4
            int d  = i >> 5;
            int c4 = i & 31;
            ((float4*)(ws + d * BN))[c4] =
                ((const float4*)(wgf + (size_t)d * K_ + k0))[c4];
        }
        if (tid < BN) wns[tid] = g_wn[(f << 9) + k0 + tid];
        __syncthreads();

        float acc[8][8];
#pragma unroll
        for (int i = 0; i < 8; ++i)
#pragma unroll
            for (int j = 0; j < 8; ++j) acc[i][j] = 0.f;

#pragma unroll 4
        for (int d = 0; d < D_; ++d) {
            float4 a0 = *(const float4*)(xs + d * BM + ty * 8);
            float4 a1 = *(const float4*)(xs + d * BM + ty * 8 + 4);
            float4 c0 = *(const float4*)(ws + d * BN + tx * 8);
            float4 c1 = *(const float4*)(ws + d * BN + tx * 8 + 4);
            float a[8] = {a0.x, a0.y, a0.z, a0.w, a1.x, a1.y, a1.z, a1.w};
            float b[8] = {c0.x, c0.y, c0.z, c0.w, c1.x, c1.y, c1.z, c1.w};
#pragma unroll
            for (int i = 0; i < 8; ++i)
#pragma unroll
                for (int j = 0; j < 8; ++j)
                    acc[i][j] = fmaf(a[i], b[j], acc[i][j]);
        }

        // epilogue: score = dot - 0.5||w||^2 ; running argmax (ties -> lower k)
#pragma unroll
        for (int j = 0; j < 8; ++j) {
            int k = k0 + tx * 8 + j;
            float wnv = wns[tx * 8 + j];
#pragma unroll
            for (int i = 0; i < 8; ++i) {
                float s = acc[i][j] - wnv;
                if (s > best[i]) { best[i] = s; bidx[i] = k; }
            }
        }
    }

    __syncthreads();  // all reads of ws done; overlay reduction area

    // cross-thread argmax reduction per row (16 tx threads share a row set)
#pragma unroll
    for (int i = 0; i < 8; ++i) {
        int row = ty * 8 + i;
        red_v[row * 16 + tx] = best[i];
        red_i[row * 16 + tx] = bidx[i];
    }
    __syncthreads();

    if (tid < BM) {
        float bv = -1e30f;
        int bk = 0;
        for (int t = 0; t < 16; ++t) {   // t ascending == k ascending
            float v = red_v[tid * 16 + t];
            int   kk = red_i[tid * 16 + t];
            if (v > bv) { bv = v; bk = kk; }
            else if (v == bv && kk < bk) { bk = kk; }
        }
        sidx[tid] = bk;
    }
    __syncthreads();

    // ---- gather quantized rows, write out, accumulate loss partial ----
    float lsum = 0.f;
    float* og = out + ((size_t)f * B_ + b0) * D_;
    for (int e = tid; e < BM * D_; e += NTHREADS) {
        int r = e >> 6;
        int d = e & 63;
        int k = sidx[r];
        float q  = g_wt[(((size_t)(f << 9)) + k) * D_ + d];
        float xv = xg[e];                 // e == r*64 + d
        og[e] = q;
        float dif = q - xv;
        lsum += dif * dif;
    }

    // block reduce (deterministic tree)
#pragma unroll
    for (int o = 16; o > 0; o >>= 1)
        lsum += __shfl_xor_sync(0xFFFFFFFFu, lsum, o);
    // xs region is free now
    if ((tid & 31) == 0) xs[tid >> 5] = lsum;
    __syncthreads();
    if (tid == 0) {
        float t = 0.f;
        for (int i = 0; i < NTHREADS / 32; ++i) t += xs[i];
        g_partial[blockIdx.y * gridDim.x + blockIdx.x] = t;
    }
}

// ---------------------------------------------------------------------------
// Final: deterministic sum of partials -> loss scalar
// ---------------------------------------------------------------------------
__global__ void vq_final(float* __restrict__ out, int nblocks, int loss_pos) {
    __shared__ float sm[8];
    int tid = threadIdx.x;
    float s = 0.f;
    for (int i = tid; i < nblocks; i += 256) s += g_partial[i];
#pragma unroll
    for (int o = 16; o > 0; o >>= 1)
        s += __shfl_xor_sync(0xFFFFFFFFu, s, o);
    if ((tid & 31) == 0) sm[tid >> 5] = s;
    __syncthreads();
    if (tid == 0) {
        float t = 0.f;
        for (int i = 0; i < 8; ++i) t += sm[i];
        // loss = 1.25 * mean((q-x)^2) over F*B*D elements
        out[loss_pos] = t * (1.25f / (float)(F_ * B_ * D_));
    }
}

// ---------------------------------------------------------------------------
extern "C" void kernel_launch(void* const* d_in, const int* in_sizes, int n_in,
                              void* d_out, int out_size) {
    const float* x = (const float*)d_in[0];   // (F,B,D)
    const float* w = (const float*)d_in[1];   // (F,D,K)
    float* out = (float*)d_out;

    cudaFuncSetAttribute(vq_main, cudaFuncAttributeMaxDynamicSharedMemorySize,
                         SMEM_BYTES);

    vq_prep<<<(F_ * K_ + 255) / 256, 256>>>(w);

    dim3 grid(B_ / BM, F_);
    vq_main<<<grid, NTHREADS, SMEM_BYTES>>>(x, w, out);

    vq_final<<<1, 256>>>(out, (B_ / BM) * F_, out_size - 1);
}

// round 2
// speedup vs baseline: 1.0863x; 1.0863x over previous
#include <cuda_runtime.h>
#include <cuda_bf16.h>
#include <cstdint>

// Problem constants
#define F_ 32
#define B_ 4096
#define D_ 64
#define K_ 512

// Tiling: block = 128 rows x (all 512 codes in 4 chunks of 128)
#define BM 128
#define BN 128
#define NTHREADS 128   // 8 (ty) x 16 (tx); thread tile 16 rows x 8 cols

typedef unsigned long long ull;

// Scratch (no allocations allowed -> __device__ globals)
__device__ float g_wt[(size_t)F_ * K_ * D_];   // transposed codebook [f][k][d]
__device__ float g_wn[F_ * K_];                // 0.5 * ||w_k||^2
__device__ float g_partial[2048];              // per-block loss partials

// packed f32x2 helpers
#define FMA_F32X2(d_, a_, b_, c_) \
    asm("fma.rn.f32x2 %0, %1, %2, %3;" : "=l"(d_) : "l"(a_), "l"(b_), "l"(c_))
#define PACK_F32X2(out_, lo_, hi_) \
    asm("mov.b64 %0, {%1, %2};" : "=l"(out_) : "f"(lo_), "f"(hi_))
#define UNPACK_F32X2(lo_, hi_, in_) \
    asm("mov.b64 {%0, %1}, %2;" : "=f"(lo_), "=f"(hi_) : "l"(in_))

// smem: xs [64][128] (32KB) | ws [64][128] (32KB) | wns[128] | sidx[128]
#define SMEM_BYTES (64 * 128 * 4 * 2 + 512 + 512)

// ---------------------------------------------------------------------------
// Prep: coalesced smem-tiled transpose  wt[f][k][d] = w[f][d][k], + 0.5||w||^2
// grid (8, 32), 256 threads; each block transposes a 64(d) x 64(k) tile
// ---------------------------------------------------------------------------
__global__ void vq_prep(const float* __restrict__ w) {
    __shared__ float ts[64][65];
    const int f  = blockIdx.y;
    const int kt = blockIdx.x;             // k-tile: codes kt*64 .. +64
    const int tid = threadIdx.x;
    const float* wf = w + (size_t)f * D_ * K_ + kt * 64;

    for (int i = tid; i < 64 * 64; i += 256) {
        int d  = i >> 6;
        int kk = i & 63;
        ts[kk][d] = wf[(size_t)d * K_ + kk];     // coalesced along k
    }
    __syncthreads();

    float* wt = g_wt + ((size_t)f * K_ + (size_t)kt * 64) * D_;
    for (int i = tid; i < 64 * 64; i += 256) {
        int kk = i >> 6;
        int d  = i & 63;
        wt[i] = ts[kk][d];                        // coalesced along d
    }
    if (tid < 64) {
        float s = 0.f;
#pragma unroll
        for (int d = 0; d < 64; ++d) { float v = ts[tid][d]; s += v * v; }
        g_wn[f * K_ + kt * 64 + tid] = 0.5f * s;
    }
}

// ---------------------------------------------------------------------------
// Main: fused distance GEMM (packed f32x2 FFMA) + argmax + gather + loss
// ---------------------------------------------------------------------------
__global__ __launch_bounds__(NTHREADS, 2)
void vq_main(const float* __restrict__ x,
             const float* __restrict__ w,
             float* __restrict__ out) {
    extern __shared__ float smem[];
    float* xs  = smem;                 // [64][128] x tile, d-major
    float* ws  = smem + 64 * 128;      // [64][128] w chunk, d-major
    float* wns = smem + 2 * 64 * 128;  // [128]
    int*   sidx = (int*)(wns + 128);   // [128]
    float* red_v = ws;                 // overlays ws after GEMM
    int*   red_i = (int*)(ws + 128 * 16);

    const int f   = blockIdx.y;
    const int b0  = blockIdx.x * BM;
    const int tid = threadIdx.x;
    const int ty  = tid >> 4;          // 0..7  -> rows ty*16 .. +16
    const int tx  = tid & 15;          // 0..15 -> cols tx*8 .. +8

    // ---- load x tile (128 rows x 64 d) transposed: xs[d][row] ----
    const float* xg = x + ((size_t)f * B_ + b0) * D_;
    for (int i = tid; i < BM * (D_ / 4); i += NTHREADS) {
        int row = i >> 4;
        int c4  = i & 15;
        float4 v = ((const float4*)(xg + (size_t)row * D_))[c4];
        int d = c4 * 4;
        xs[(d + 0) * BM + row] = v.x;
        xs[(d + 1) * BM + row] = v.y;
        xs[(d + 2) * BM + row] = v.z;
        xs[(d + 3) * BM + row] = v.w;
    }

    float best[16];
    int   bidx[16];
#pragma unroll
    for (int i = 0; i < 16; ++i) { best[i] = -1e30f; bidx[i] = 0; }

    const float* wgf = w + (size_t)f * D_ * K_;

    for (int k0 = 0; k0 < K_; k0 += BN) {
        __syncthreads();

        // load w chunk: ws[d][kk] = w[f][d][k0+kk] (k-contiguous, coalesced)
        for (int i = tid; i < D_ * (BN / 4); i += NTHREADS) {
            int d  = i >> 5;
            int c4 = i & 31;
            ((float4*)(ws + d * BN))[c4] =
                ((const float4*)(wgf + (size_t)d * K_ + k0))[c4];
        }
        if (tid < BN) wns[tid] = g_wn[(f << 9) + k0 + tid];
        __syncthreads();

        // acc[i2][j]: packed pair of rows (2*i2, 2*i2+1) x code j
        ull acc[8][8];
#pragma unroll
        for (int i = 0; i < 8; ++i)
#pragma unroll
            for (int j = 0; j < 8; ++j) acc[i][j] = 0ULL;

#pragma unroll 4
        for (int d = 0; d < D_; ++d) {
            // a: 16 consecutive rows -> 8 packed f32x2 (direct vector loads)
            const ulonglong2* ap =
                (const ulonglong2*)(xs + d * BM + ty * 16);
            ulonglong2 av0 = ap[0], av1 = ap[1], av2 = ap[2], av3 = ap[3];
            ull a[8] = {av0.x, av0.y, av1.x, av1.y,
                        av2.x, av2.y, av3.x, av3.y};
            // b: 8 scalar codes, duplicated into both halves
            float4 c0 = *(const float4*)(ws + d * BN + tx * 8);
            float4 c1 = *(const float4*)(ws + d * BN + tx * 8 + 4);
            float bsc[8] = {c0.x, c0.y, c0.z, c0.w, c1.x, c1.y, c1.z, c1.w};
            ull bb[8];
#pragma unroll
            for (int j = 0; j < 8; ++j) PACK_F32X2(bb[j], bsc[j], bsc[j]);
#pragma unroll
            for (int i = 0; i < 8; ++i)
#pragma unroll
                for (int j = 0; j < 8; ++j)
                    FMA_F32X2(acc[i][j], a[i], bb[j], acc[i][j]);
        }

        // epilogue: score = dot - 0.5||w||^2; running argmax (k ascending)
#pragma unroll
        for (int j = 0; j < 8; ++j) {
            int k = k0 + tx * 8 + j;
            float wnv = wns[tx * 8 + j];
#pragma unroll
            for (int i = 0; i < 8; ++i) {
                float s0, s1;
                UNPACK_F32X2(s0, s1, acc[i][j]);
                s0 -= wnv; s1 -= wnv;
                if (s0 > best[2 * i])     { best[2 * i] = s0;     bidx[2 * i] = k; }
                if (s1 > best[2 * i + 1]) { best[2 * i + 1] = s1; bidx[2 * i + 1] = k; }
            }
        }
    }

    __syncthreads();  // all ws reads done; overlay reduction area

    // per-row cross-thread argmax (16 tx candidates per row)
#pragma unroll
    for (int i = 0; i < 16; ++i) {
        int row = ty * 16 + i;
        red_v[row * 16 + tx] = best[i];
        red_i[row * 16 + tx] = bidx[i];
    }
    __syncthreads();

    {
        int row = tid;   // 128 threads, 128 rows
        float bv = -1e30f;
        int bk = 0;
        for (int t = 0; t < 16; ++t) {       // t ascending == k ascending
            float v = red_v[row * 16 + t];
            int  kk = red_i[row * 16 + t];
            if (v > bv) { bv = v; bk = kk; }
            else if (v == bv && kk < bk) { bk = kk; }
        }
        sidx[row] = bk;
    }
    __syncthreads();

    // ---- gather quantized rows, write out, accumulate loss partial ----
    float lsum = 0.f;
    float* og = out + ((size_t)f * B_ + b0) * D_;
    for (int e = tid; e < BM * D_; e += NTHREADS) {
        int r = e >> 6;
        int d = e & 63;
        int k = sidx[r];
        float q  = g_wt[(((size_t)(f << 9)) + k) * D_ + d];
        float xv = xg[e];
        og[e] = q;
        float dif = q - xv;
        lsum += dif * dif;
    }

#pragma unroll
    for (int o = 16; o > 0; o >>= 1)
        lsum += __shfl_xor_sync(0xFFFFFFFFu, lsum, o);
    if ((tid & 31) == 0) xs[tid >> 5] = lsum;   // xs free now
    __syncthreads();
    if (tid == 0) {
        float t = 0.f;
        for (int i = 0; i < NTHREADS / 32; ++i) t += xs[i];
        g_partial[blockIdx.y * gridDim.x + blockIdx.x] = t;
    }
}

// ---------------------------------------------------------------------------
__global__ void vq_final(float* __restrict__ out, int nblocks, int loss_pos) {
    __shared__ float sm[8];
    int tid = threadIdx.x;
    float s = 0.f;
    for (int i = tid; i < nblocks; i += 256) s += g_partial[i];
#pragma unroll
    for (int o = 16; o > 0; o >>= 1)
        s += __shfl_xor_sync(0xFFFFFFFFu, s, o);
    if ((tid & 31) == 0) sm[tid >> 5] = s;
    __syncthreads();
    if (tid == 0) {
        float t = 0.f;
        for (int i = 0; i < 8; ++i) t += sm[i];
        out[loss_pos] = t * (1.25f / (float)(F_ * B_ * D_));
    }
}

// ---------------------------------------------------------------------------
extern "C" void kernel_launch(void* const* d_in, const int* in_sizes, int n_in,
                              void* d_out, int out_size) {
    const float* x = (const float*)d_in[0];   // (F,B,D)
    const float* w = (const float*)d_in[1];   // (F,D,K)
    float* out = (float*)d_out;

    cudaFuncSetAttribute(vq_main, cudaFuncAttributeMaxDynamicSharedMemorySize,
                         SMEM_BYTES);

    dim3 pgrid(8, 32);
    vq_prep<<<pgrid, 256>>>(w);

    dim3 grid(B_ / BM, F_);
    vq_main<<<grid, NTHREADS, SMEM_BYTES>>>(x, w, out);

    vq_final<<<1, 256>>>(out, (B_ / BM) * F_, out_size - 1);
}